// round 4
// baseline (speedup 1.0000x reference)
#include <cuda_runtime.h>
#include <cuda_fp16.h>
#include <cstdint>
#include <math.h>

#define DI __device__ __forceinline__

// ---------------- problem sizes ----------------
constexpr int BB   = 4;
constexpr int LL   = 8192;
constexpr int DD   = 1024;
constexpr int MTOT = BB * LL;     // 32768
constexpr int KTOT = 1024;

// GEMM tiling (fp16 operands, fp32 accum)
constexpr int BM = 128, BN = 256, BK = 32;
constexpr int NKC = KTOT / BK;            // 32
constexpr int KP  = 40;                   // smem pitch in halfs (80B rows, conflict-free)
constexpr int ASTAGE = BM * KP;           // 5120 halfs
constexpr int BSTAGE = BN * KP;           // 10240 halfs
constexpr int STAGE_H = ASTAGE + BSTAGE;  // 15360 halfs = 30720 B
constexpr int STAGES = 5;
constexpr int SMEM_BYTES = STAGES * STAGE_H * 2;   // 153600

// scan chunking
constexpr int NC = 64;
constexpr int CL = LL / NC;               // 128
constexpr int NCHAIN = BB * DD;           // 4096

// ---------------- device scratch ----------------
__device__ __half g_xh[(size_t)MTOT * KTOT];    // fp16 x
__device__ __half g_wh[(size_t)4 * DD * KTOT];  // fp16 weights, [gate][n][k]
__device__ float g_f [(size_t)MTOT * DD];
__device__ float g_ti[(size_t)MTOT * DD];
__device__ float g_si[(size_t)MTOT * DD];
__device__ float g_og[(size_t)MTOT * DD];
__device__ float g_cA[NC * NCHAIN];
__device__ float g_cB[NC * NCHAIN];
__device__ float g_cr[NC * NCHAIN];

// ---------------- helpers ----------------
DI uint32_t smem_u32(const void* p) {
    uint32_t a;
    asm("{ .reg .u64 t; cvta.to.shared.u64 t, %1; cvt.u32.u64 %0, t; }" : "=r"(a) : "l"(p));
    return a;
}
DI void cp16(uint32_t dst, const void* src) {
    asm volatile("cp.async.cg.shared.global [%0], [%1], 16;" :: "r"(dst), "l"(src));
}
DI void cp_commit() { asm volatile("cp.async.commit_group;" ::: "memory"); }
template <int N> DI void cp_wait() {
    asm volatile("cp.async.wait_group %0;" :: "n"(N) : "memory");
}
DI void ldsm4(uint32_t& r0, uint32_t& r1, uint32_t& r2, uint32_t& r3, uint32_t addr) {
    asm volatile("ldmatrix.sync.aligned.m8n8.x4.shared.b16 {%0,%1,%2,%3}, [%4];"
                 : "=r"(r0), "=r"(r1), "=r"(r2), "=r"(r3) : "r"(addr));
}
DI void mma_f16(float& c0, float& c1, float& c2, float& c3,
                uint32_t a0, uint32_t a1, uint32_t a2, uint32_t a3,
                uint32_t b0, uint32_t b1) {
    asm volatile(
        "mma.sync.aligned.m16n8k16.row.col.f32.f16.f16.f32 "
        "{%0,%1,%2,%3}, {%4,%5,%6,%7}, {%8,%9}, {%0,%1,%2,%3};"
        : "+f"(c0), "+f"(c1), "+f"(c2), "+f"(c3)
        : "r"(a0), "r"(a1), "r"(a2), "r"(a3), "r"(b0), "r"(b1));
}
DI float sigf(float z) { return 1.0f / (1.0f + __expf(-z)); }
DI float tanhfast(float z) { return 1.0f - 2.0f / (1.0f + __expf(2.0f * z)); }

// ---------------- prep: fp32 -> fp16 ----------------
__global__ void prep_x_kernel(const float* __restrict__ x) {
    size_t i = (size_t)blockIdx.x * blockDim.x + threadIdx.x;
    float4 v0 = reinterpret_cast<const float4*>(x)[2 * i];
    float4 v1 = reinterpret_cast<const float4*>(x)[2 * i + 1];
    __half2 h[4];
    h[0] = __floats2half2_rn(v0.x, v0.y);
    h[1] = __floats2half2_rn(v0.z, v0.w);
    h[2] = __floats2half2_rn(v1.x, v1.y);
    h[3] = __floats2half2_rn(v1.z, v1.w);
    reinterpret_cast<uint4*>(g_xh)[i] = *reinterpret_cast<uint4*>(h);
}

__global__ void prep_w_kernel(const float* __restrict__ Wf, const float* __restrict__ Wi,
                              const float* __restrict__ Wig, const float* __restrict__ Wog) {
    __shared__ float t[32][33];
    int g = blockIdx.z;
    const float* W = (g == 0) ? Wf : (g == 1) ? Wi : (g == 2) ? Wig : Wog;
    int n0 = blockIdx.x * 32, k0 = blockIdx.y * 32;
    int tx = threadIdx.x, ty = threadIdx.y;
    t[ty][tx] = W[(size_t)(k0 + ty) * 1024 + n0 + tx];
    __syncthreads();
    g_wh[(size_t)(g * 1024 + n0 + ty) * 1024 + (k0 + tx)] = __float2half_rn(t[tx][ty]);
}

// ---------------- fp16 GEMM (128x256 CTA tile, 64x64 warp tiles) ----------------
__global__ void __launch_bounds__(256, 1)
gemm_kernel(const float* __restrict__ bf, const float* __restrict__ bi,
            const float* __restrict__ big, const float* __restrict__ bog) {
    extern __shared__ __half sm[];
    const uint32_t sb = smem_u32(sm);

    const int tid  = threadIdx.x;
    const int wid  = tid >> 5, lane = tid & 31;
    const int lane4 = lane & 3, laneg = lane >> 2;
    const int warpM = wid & 1;          // 2 warps along M (64 rows each)
    const int warpN = wid >> 1;         // 4 warps along N (64 cols each)
    const int nTile = blockIdx.x;       // 0..15
    const int mTile = blockIdx.y;       // 0..255
    const int g     = nTile >> 2;       // gate
    const int nbase = (nTile & 3) * BN; // col offset inside gate

    const __half* Abase = g_xh + (size_t)mTile * BM * KTOT;
    const __half* Bbase = g_wh + ((size_t)g * DD + nbase) * KTOT;

    auto load_chunk = [&](int kc, int s) {
        const uint32_t sA = sb + s * (STAGE_H * 2);
        const uint32_t sB = sA + ASTAGE * 2;
        const __half* gA = Abase + kc * BK;
        const __half* gB = Bbase + kc * BK;
        #pragma unroll
        for (int i = 0; i < 2; i++) {                 // A: 512 x 16B chunks
            int c = tid + i * 256;
            int row = c >> 2, seg = (c & 3) * 8;
            cp16(sA + (row * KP + seg) * 2, gA + (size_t)row * KTOT + seg);
        }
        #pragma unroll
        for (int i = 0; i < 4; i++) {                 // B: 1024 x 16B chunks
            int c = tid + i * 256;
            int row = c >> 2, seg = (c & 3) * 8;
            cp16(sB + (row * KP + seg) * 2, gB + (size_t)row * KTOT + seg);
        }
        cp_commit();
    };

    float acc[4][8][4];
    #pragma unroll
    for (int mf = 0; mf < 4; mf++)
        #pragma unroll
        for (int nf = 0; nf < 8; nf++)
            #pragma unroll
            for (int j = 0; j < 4; j++) acc[mf][nf][j] = 0.0f;

    // per-thread ldmatrix byte offsets (within a stage)
    uint32_t aOff[4], bOff[4];
    #pragma unroll
    for (int mf = 0; mf < 4; mf++)
        aOff[mf] = (uint32_t)(((warpM * 64 + mf * 16 + (lane & 15)) * KP + (lane >> 4) * 8) * 2);
    #pragma unroll
    for (int p = 0; p < 4; p++)
        bOff[p] = (uint32_t)(((warpN * 64 + p * 16 + (lane & 7) + (lane >> 4) * 8) * KP
                              + ((lane >> 3) & 1) * 8) * 2) + ASTAGE * 2;

    load_chunk(0, 0);
    load_chunk(1, 1);
    load_chunk(2, 2);
    load_chunk(3, 3);

    for (int kc = 0; kc < NKC; kc++) {
        const int s = kc % STAGES;
        if (kc + 3 < NKC)      cp_wait<3>();
        else if (kc + 2 < NKC) cp_wait<2>();
        else if (kc + 1 < NKC) cp_wait<1>();
        else                   cp_wait<0>();
        __syncthreads();
        if (kc + 4 < NKC) load_chunk(kc + 4, (kc + 4) % STAGES);

        const uint32_t st = sb + s * (STAGE_H * 2);
        #pragma unroll
        for (int kf = 0; kf < 2; kf++) {
            const uint32_t kb = kf * 32;              // 16 halfs = 32 bytes
            uint32_t a[4][4];
            #pragma unroll
            for (int mf = 0; mf < 4; mf++)
                ldsm4(a[mf][0], a[mf][1], a[mf][2], a[mf][3], st + aOff[mf] + kb);
            uint32_t b[8][2];
            #pragma unroll
            for (int p = 0; p < 4; p++)
                ldsm4(b[2 * p][0], b[2 * p][1], b[2 * p + 1][0], b[2 * p + 1][1],
                      st + bOff[p] + kb);
            #pragma unroll
            for (int mf = 0; mf < 4; mf++)
                #pragma unroll
                for (int nf = 0; nf < 8; nf++)
                    mma_f16(acc[mf][nf][0], acc[mf][nf][1], acc[mf][nf][2], acc[mf][nf][3],
                            a[mf][0], a[mf][1], a[mf][2], a[mf][3],
                            b[nf][0], b[nf][1]);
        }
    }

    // epilogue: bias + activation, write gate array
    const float* bias = (g == 0) ? bf : (g == 1) ? bi : (g == 2) ? big : bog;
    float* oA = (g == 0) ? g_f : (g == 1) ? g_ti : (g == 2) ? g_si : g_og;
    const bool isTanh = (g == 1);
    #pragma unroll
    for (int nf = 0; nf < 8; nf++) {
        const int d = nbase + warpN * 64 + nf * 8 + 2 * lane4;
        const float bz0 = bias[d], bz1 = bias[d + 1];
        #pragma unroll
        for (int mf = 0; mf < 4; mf++) {
            const int r0 = mTile * BM + warpM * 64 + mf * 16 + laneg;
            float z0 = acc[mf][nf][0] + bz0;
            float z1 = acc[mf][nf][1] + bz1;
            float z2 = acc[mf][nf][2] + bz0;
            float z3 = acc[mf][nf][3] + bz1;
            float2 o0, o1;
            if (isTanh) { o0.x = tanhfast(z0); o0.y = tanhfast(z1);
                          o1.x = tanhfast(z2); o1.y = tanhfast(z3); }
            else        { o0.x = sigf(z0); o0.y = sigf(z1);
                          o1.x = sigf(z2); o1.y = sigf(z3); }
            *reinterpret_cast<float2*>(oA + (size_t)r0 * DD + d) = o0;
            *reinterpret_cast<float2*>(oA + (size_t)(r0 + 8) * DD + d) = o1;
        }
    }
}

// ---------------- scan kernels ----------------
__global__ void scan_pass1() {
    int d = blockIdx.x * 256 + threadIdx.x;
    int c = blockIdx.y, b = blockIdx.z;
    size_t base = ((size_t)(b * LL + c * CL)) * DD + d;
    float a = 1.0f, accv = 0.0f;
    for (int t = 0; t < CL; t++) {
        size_t idx = base + (size_t)t * DD;
        float F = g_f[idx];
        float I = g_ti[idx] * g_si[idx];
        accv = fmaf(F, accv, I);
        a *= F;
    }
    int chain = b * DD + d;
    g_cA[c * NCHAIN + chain] = a;
    g_cB[c * NCHAIN + chain] = accv;
}

__global__ void scan_pass2(const float* __restrict__ lh) {
    int chain = blockIdx.x * 256 + threadIdx.x;     // 0..4095
    float carry = lh[chain & (DD - 1)];
    for (int c = 0; c < NC; c++) {
        g_cr[c * NCHAIN + chain] = carry;
        carry = fmaf(g_cA[c * NCHAIN + chain], carry, g_cB[c * NCHAIN + chain]);
    }
}

__global__ void scan_pass3(float* __restrict__ y) {
    int d = blockIdx.x * 256 + threadIdx.x;
    int c = blockIdx.y, b = blockIdx.z;
    int chain = b * DD + d;
    float h = g_cr[c * NCHAIN + chain];
    size_t base = ((size_t)(b * LL + c * CL)) * DD + d;
    for (int t = 0; t < CL; t++) {
        size_t idx = base + (size_t)t * DD;
        float F = g_f[idx];
        float I = g_ti[idx] * g_si[idx];
        h = fmaf(F, h, I);
        y[idx] = tanhfast(h) * g_og[idx];
    }
}

// ---------------- launch ----------------
extern "C" void kernel_launch(void* const* d_in, const int* in_sizes, int n_in,
                              void* d_out, int out_size) {
    const float* x   = (const float*)d_in[0];
    const float* Wf  = (const float*)d_in[1];
    const float* bf  = (const float*)d_in[2];
    const float* Wi  = (const float*)d_in[3];
    const float* bi  = (const float*)d_in[4];
    const float* Wig = (const float*)d_in[5];
    const float* big = (const float*)d_in[6];
    const float* Wog = (const float*)d_in[7];
    const float* bog = (const float*)d_in[8];
    const float* lh  = (const float*)d_in[9];
    float* y = (float*)d_out;

    cudaFuncSetAttribute(gemm_kernel, cudaFuncAttributeMaxDynamicSharedMemorySize, SMEM_BYTES);

    prep_x_kernel<<<16384, 256>>>(x);
    prep_w_kernel<<<dim3(32, 32, 4), dim3(32, 32)>>>(Wf, Wi, Wig, Wog);
    gemm_kernel<<<dim3(16, 256), 256, SMEM_BYTES>>>(bf, bi, big, bog);
    scan_pass1<<<dim3(4, NC, 4), 256>>>();
    scan_pass2<<<16, 256>>>(lh);
    scan_pass3<<<dim3(4, NC, 4), 256>>>(y);
}

// round 5
// speedup vs baseline: 1.1010x; 1.1010x over previous
#include <cuda_runtime.h>
#include <cuda_fp16.h>
#include <cstdint>
#include <math.h>

#define DI __device__ __forceinline__

// ---------------- problem sizes ----------------
constexpr int BB   = 4;
constexpr int LL   = 8192;
constexpr int DD   = 1024;
constexpr int MTOT = BB * LL;     // 32768
constexpr int KTOT = 1024;

// GEMM tiling: 128x128 CTA tile, 4 warps (2x2), 64x64 warp tiles, 2 CTAs/SM
constexpr int BM = 128, BN = 128, BK = 32;
constexpr int NKC = KTOT / BK;            // 32
constexpr int KP  = 40;                   // smem pitch in halfs (80B rows, conflict-free)
constexpr int ASTAGE = BM * KP;           // 5120 halfs
constexpr int BSTAGE = BN * KP;           // 5120 halfs
constexpr int STAGE_H = ASTAGE + BSTAGE;  // 10240 halfs = 20480 B
constexpr int STAGES = 4;
constexpr int SMEM_BYTES = STAGES * STAGE_H * 2;   // 81920 B -> 2 CTAs/SM

// scan chunking
constexpr int NC = 64;
constexpr int CL = LL / NC;               // 128
constexpr int NCHAIN = BB * DD;           // 4096

// ---------------- device scratch ----------------
__device__ __half g_xh[(size_t)MTOT * KTOT];    // fp16 x
__device__ __half g_wh[(size_t)4 * DD * KTOT];  // fp16 weights, [gate][n][k]
__device__ __half g_f [(size_t)MTOT * DD];      // gates stored fp16
__device__ __half g_ti[(size_t)MTOT * DD];
__device__ __half g_si[(size_t)MTOT * DD];
__device__ __half g_og[(size_t)MTOT * DD];
__device__ float g_cA[NC * NCHAIN];
__device__ float g_cB[NC * NCHAIN];
__device__ float g_cr[NC * NCHAIN];

// ---------------- helpers ----------------
DI uint32_t smem_u32(const void* p) {
    uint32_t a;
    asm("{ .reg .u64 t; cvta.to.shared.u64 t, %1; cvt.u32.u64 %0, t; }" : "=r"(a) : "l"(p));
    return a;
}
DI void cp16(uint32_t dst, const void* src) {
    asm volatile("cp.async.cg.shared.global [%0], [%1], 16;" :: "r"(dst), "l"(src));
}
DI void cp_commit() { asm volatile("cp.async.commit_group;" ::: "memory"); }
template <int N> DI void cp_wait() {
    asm volatile("cp.async.wait_group %0;" :: "n"(N) : "memory");
}
DI void ldsm4(uint32_t& r0, uint32_t& r1, uint32_t& r2, uint32_t& r3, uint32_t addr) {
    asm volatile("ldmatrix.sync.aligned.m8n8.x4.shared.b16 {%0,%1,%2,%3}, [%4];"
                 : "=r"(r0), "=r"(r1), "=r"(r2), "=r"(r3) : "r"(addr));
}
DI void mma_f16(float& c0, float& c1, float& c2, float& c3,
                uint32_t a0, uint32_t a1, uint32_t a2, uint32_t a3,
                uint32_t b0, uint32_t b1) {
    asm volatile(
        "mma.sync.aligned.m16n8k16.row.col.f32.f16.f16.f32 "
        "{%0,%1,%2,%3}, {%4,%5,%6,%7}, {%8,%9}, {%0,%1,%2,%3};"
        : "+f"(c0), "+f"(c1), "+f"(c2), "+f"(c3)
        : "r"(a0), "r"(a1), "r"(a2), "r"(a3), "r"(b0), "r"(b1));
}
DI float sigf(float z) { return 1.0f / (1.0f + __expf(-z)); }
DI float tanhfast(float z) { return 1.0f - 2.0f / (1.0f + __expf(2.0f * z)); }

// ---------------- prep: fp32 -> fp16 ----------------
__global__ void prep_x_kernel(const float* __restrict__ x) {
    size_t i = (size_t)blockIdx.x * blockDim.x + threadIdx.x;
    float4 v0 = reinterpret_cast<const float4*>(x)[2 * i];
    float4 v1 = reinterpret_cast<const float4*>(x)[2 * i + 1];
    __half2 h[4];
    h[0] = __floats2half2_rn(v0.x, v0.y);
    h[1] = __floats2half2_rn(v0.z, v0.w);
    h[2] = __floats2half2_rn(v1.x, v1.y);
    h[3] = __floats2half2_rn(v1.z, v1.w);
    reinterpret_cast<uint4*>(g_xh)[i] = *reinterpret_cast<uint4*>(h);
}

__global__ void prep_w_kernel(const float* __restrict__ Wf, const float* __restrict__ Wi,
                              const float* __restrict__ Wig, const float* __restrict__ Wog) {
    __shared__ float t[32][33];
    int g = blockIdx.z;
    const float* W = (g == 0) ? Wf : (g == 1) ? Wi : (g == 2) ? Wig : Wog;
    int n0 = blockIdx.x * 32, k0 = blockIdx.y * 32;
    int tx = threadIdx.x, ty = threadIdx.y;
    t[ty][tx] = W[(size_t)(k0 + ty) * 1024 + n0 + tx];
    __syncthreads();
    g_wh[(size_t)(g * 1024 + n0 + ty) * 1024 + (k0 + tx)] = __float2half_rn(t[tx][ty]);
}

// ---------------- fp16 GEMM (128x128 CTA, 4 warps, 64x64 warp tiles) ----------------
__global__ void __launch_bounds__(128)
gemm_kernel(const float* __restrict__ bf, const float* __restrict__ bi,
            const float* __restrict__ big, const float* __restrict__ bog) {
    extern __shared__ __half sm[];
    const uint32_t sb = smem_u32(sm);

    const int tid  = threadIdx.x;
    const int wid  = tid >> 5, lane = tid & 31;
    const int lane4 = lane & 3, laneg = lane >> 2;
    const int warpM = wid & 1;          // 2 warps along M (64 rows each)
    const int warpN = wid >> 1;         // 2 warps along N (64 cols each)
    const int nTile = blockIdx.x;       // 0..31
    const int mTile = blockIdx.y;       // 0..255
    const int g     = nTile >> 3;       // gate
    const int nbase = (nTile & 7) * BN; // col offset inside gate

    const __half* Abase = g_xh + (size_t)mTile * BM * KTOT;
    const __half* Bbase = g_wh + ((size_t)g * DD + nbase) * KTOT;

    auto load_chunk = [&](int kc, int s) {
        const uint32_t sA = sb + s * (STAGE_H * 2);
        const uint32_t sB = sA + ASTAGE * 2;
        const __half* gA = Abase + kc * BK;
        const __half* gB = Bbase + kc * BK;
        #pragma unroll
        for (int i = 0; i < 4; i++) {                 // A: 512 x 16B chunks
            int c = tid + i * 128;
            int row = c >> 2, seg = (c & 3) * 8;
            cp16(sA + (row * KP + seg) * 2, gA + (size_t)row * KTOT + seg);
        }
        #pragma unroll
        for (int i = 0; i < 4; i++) {                 // B: 512 x 16B chunks
            int c = tid + i * 128;
            int row = c >> 2, seg = (c & 3) * 8;
            cp16(sB + (row * KP + seg) * 2, gB + (size_t)row * KTOT + seg);
        }
        cp_commit();
    };

    float acc[4][8][4];
    #pragma unroll
    for (int mf = 0; mf < 4; mf++)
        #pragma unroll
        for (int nf = 0; nf < 8; nf++)
            #pragma unroll
            for (int j = 0; j < 4; j++) acc[mf][nf][j] = 0.0f;

    // per-thread ldmatrix byte offsets (within a stage)
    uint32_t aOff[4], bOff[4];
    #pragma unroll
    for (int mf = 0; mf < 4; mf++)
        aOff[mf] = (uint32_t)(((warpM * 64 + mf * 16 + (lane & 15)) * KP + (lane >> 4) * 8) * 2);
    #pragma unroll
    for (int p = 0; p < 4; p++)
        bOff[p] = (uint32_t)(((warpN * 64 + p * 16 + (lane & 7) + (lane >> 4) * 8) * KP
                              + ((lane >> 3) & 1) * 8) * 2) + ASTAGE * 2;

    load_chunk(0, 0);
    load_chunk(1, 1);
    load_chunk(2, 2);

    for (int kc = 0; kc < NKC; kc++) {
        const int s = kc & 3;
        if (kc + 2 < NKC)      cp_wait<2>();
        else if (kc + 1 < NKC) cp_wait<1>();
        else                   cp_wait<0>();
        __syncthreads();
        if (kc + 3 < NKC) load_chunk(kc + 3, (kc + 3) & 3);

        const uint32_t st = sb + s * (STAGE_H * 2);
        #pragma unroll
        for (int kf = 0; kf < 2; kf++) {
            const uint32_t kb = kf * 32;              // 16 halfs = 32 bytes
            uint32_t a[4][4];
            #pragma unroll
            for (int mf = 0; mf < 4; mf++)
                ldsm4(a[mf][0], a[mf][1], a[mf][2], a[mf][3], st + aOff[mf] + kb);
            uint32_t b[8][2];
            #pragma unroll
            for (int p = 0; p < 4; p++)
                ldsm4(b[2 * p][0], b[2 * p][1], b[2 * p + 1][0], b[2 * p + 1][1],
                      st + bOff[p] + kb);
            #pragma unroll
            for (int mf = 0; mf < 4; mf++)
                #pragma unroll
                for (int nf = 0; nf < 8; nf++)
                    mma_f16(acc[mf][nf][0], acc[mf][nf][1], acc[mf][nf][2], acc[mf][nf][3],
                            a[mf][0], a[mf][1], a[mf][2], a[mf][3],
                            b[nf][0], b[nf][1]);
        }
    }

    // epilogue: bias + activation, write fp16 gate array
    const float* bias = (g == 0) ? bf : (g == 1) ? bi : (g == 2) ? big : bog;
    __half* oA = (g == 0) ? g_f : (g == 1) ? g_ti : (g == 2) ? g_si : g_og;
    const bool isTanh = (g == 1);
    #pragma unroll
    for (int nf = 0; nf < 8; nf++) {
        const int d = nbase + warpN * 64 + nf * 8 + 2 * lane4;
        const float bz0 = bias[d], bz1 = bias[d + 1];
        #pragma unroll
        for (int mf = 0; mf < 4; mf++) {
            const int r0 = mTile * BM + warpM * 64 + mf * 16 + laneg;
            float z0 = acc[mf][nf][0] + bz0;
            float z1 = acc[mf][nf][1] + bz1;
            float z2 = acc[mf][nf][2] + bz0;
            float z3 = acc[mf][nf][3] + bz1;
            float o0, o1, o2, o3;
            if (isTanh) { o0 = tanhfast(z0); o1 = tanhfast(z1);
                          o2 = tanhfast(z2); o3 = tanhfast(z3); }
            else        { o0 = sigf(z0); o1 = sigf(z1);
                          o2 = sigf(z2); o3 = sigf(z3); }
            *reinterpret_cast<__half2*>(oA + (size_t)r0 * DD + d) = __floats2half2_rn(o0, o1);
            *reinterpret_cast<__half2*>(oA + (size_t)(r0 + 8) * DD + d) = __floats2half2_rn(o2, o3);
        }
    }
}

// ---------------- scan kernels (2 chains per thread via half2) ----------------
__global__ void scan_pass1() {
    int p = blockIdx.x * 256 + threadIdx.x;         // 0..511 half2 lane
    int c = blockIdx.y, b = blockIdx.z;
    size_t base = ((size_t)(b * LL + c * CL)) * (DD / 2) + p;
    const __half2* F2p  = reinterpret_cast<const __half2*>(g_f);
    const __half2* Ti2p = reinterpret_cast<const __half2*>(g_ti);
    const __half2* Si2p = reinterpret_cast<const __half2*>(g_si);
    float2 a = make_float2(1.0f, 1.0f);
    float2 s = make_float2(0.0f, 0.0f);
    for (int t = 0; t < CL; t++) {
        size_t idx = base + (size_t)t * (DD / 2);
        float2 F = __half22float2(F2p[idx]);
        float2 Ti = __half22float2(Ti2p[idx]);
        float2 Si = __half22float2(Si2p[idx]);
        s.x = fmaf(F.x, s.x, Ti.x * Si.x);
        s.y = fmaf(F.y, s.y, Ti.y * Si.y);
        a.x *= F.x; a.y *= F.y;
    }
    int chain = b * DD + 2 * p;
    g_cA[c * NCHAIN + chain]     = a.x;
    g_cA[c * NCHAIN + chain + 1] = a.y;
    g_cB[c * NCHAIN + chain]     = s.x;
    g_cB[c * NCHAIN + chain + 1] = s.y;
}

__global__ void scan_pass2(const float* __restrict__ lh) {
    int chain = blockIdx.x * 256 + threadIdx.x;     // 0..4095
    float carry = lh[chain & (DD - 1)];
    for (int c = 0; c < NC; c++) {
        g_cr[c * NCHAIN + chain] = carry;
        carry = fmaf(g_cA[c * NCHAIN + chain], carry, g_cB[c * NCHAIN + chain]);
    }
}

__global__ void scan_pass3(float* __restrict__ y) {
    int p = blockIdx.x * 256 + threadIdx.x;         // 0..511 half2 lane
    int c = blockIdx.y, b = blockIdx.z;
    int chain = b * DD + 2 * p;
    float2 h;
    h.x = g_cr[c * NCHAIN + chain];
    h.y = g_cr[c * NCHAIN + chain + 1];
    size_t base = ((size_t)(b * LL + c * CL)) * (DD / 2) + p;
    const __half2* F2p  = reinterpret_cast<const __half2*>(g_f);
    const __half2* Ti2p = reinterpret_cast<const __half2*>(g_ti);
    const __half2* Si2p = reinterpret_cast<const __half2*>(g_si);
    const __half2* Og2p = reinterpret_cast<const __half2*>(g_og);
    for (int t = 0; t < CL; t++) {
        size_t idx = base + (size_t)t * (DD / 2);
        float2 F = __half22float2(F2p[idx]);
        float2 Ti = __half22float2(Ti2p[idx]);
        float2 Si = __half22float2(Si2p[idx]);
        float2 Og = __half22float2(Og2p[idx]);
        h.x = fmaf(F.x, h.x, Ti.x * Si.x);
        h.y = fmaf(F.y, h.y, Ti.y * Si.y);
        float2 o;
        o.x = tanhfast(h.x) * Og.x;
        o.y = tanhfast(h.y) * Og.y;
        reinterpret_cast<float2*>(y)[idx] = o;
    }
}

// ---------------- launch ----------------
extern "C" void kernel_launch(void* const* d_in, const int* in_sizes, int n_in,
                              void* d_out, int out_size) {
    const float* x   = (const float*)d_in[0];
    const float* Wf  = (const float*)d_in[1];
    const float* bf  = (const float*)d_in[2];
    const float* Wi  = (const float*)d_in[3];
    const float* bi  = (const float*)d_in[4];
    const float* Wig = (const float*)d_in[5];
    const float* big = (const float*)d_in[6];
    const float* Wog = (const float*)d_in[7];
    const float* bog = (const float*)d_in[8];
    const float* lh  = (const float*)d_in[9];
    float* y = (float*)d_out;

    cudaFuncSetAttribute(gemm_kernel, cudaFuncAttributeMaxDynamicSharedMemorySize, SMEM_BYTES);

    prep_x_kernel<<<16384, 256>>>(x);
    prep_w_kernel<<<dim3(32, 32, 4), dim3(32, 32)>>>(Wf, Wi, Wig, Wog);
    gemm_kernel<<<dim3(32, 256), 128, SMEM_BYTES>>>(bf, bi, big, bog);
    scan_pass1<<<dim3(2, NC, 4), 256>>>();
    scan_pass2<<<16, 256>>>(lh);
    scan_pass3<<<dim3(2, NC, 4), 256>>>(y);
}

// round 7
// speedup vs baseline: 1.1600x; 1.0536x over previous
#include <cuda_runtime.h>
#include <cuda_fp16.h>
#include <cstdint>
#include <math.h>

#define DI __device__ __forceinline__

// ---------------- problem sizes ----------------
constexpr int BB   = 4;
constexpr int LL   = 8192;
constexpr int DD   = 1024;
constexpr int MTOT = BB * LL;     // 32768
constexpr int KTOT = 1024;

// GEMM tiling: 256x128 CTA tile, 16 warps (8Mx2N), 32x64 warp tiles
constexpr int BM = 256, BN = 128, BK = 32;
constexpr int NKC = KTOT / BK;            // 32
constexpr int KP  = 40;                   // smem pitch in halfs (80B rows, conflict-free)
constexpr int ASTAGE = BM * KP;           // 10240 halfs
constexpr int BSTAGE = BN * KP;           // 5120 halfs
constexpr int STAGE_H = ASTAGE + BSTAGE;  // 15360 halfs = 30720 B
constexpr int STAGES = 5;
constexpr int SMEM_BYTES = STAGES * STAGE_H * 2;   // 153600 B

// scan chunking
constexpr int NC = 64;
constexpr int CL = LL / NC;               // 128
constexpr int NCHAIN = BB * DD;           // 4096

// ---------------- device scratch ----------------
__device__ __half g_xh[(size_t)MTOT * KTOT];    // fp16 x
__device__ __half g_wh[(size_t)4 * DD * KTOT];  // fp16 weights, [gate][n][k]
__device__ __half g_f [(size_t)MTOT * DD];      // gates stored fp16
__device__ __half g_ti[(size_t)MTOT * DD];
__device__ __half g_si[(size_t)MTOT * DD];
__device__ __half g_og[(size_t)MTOT * DD];
__device__ float g_cA[NC * NCHAIN];
__device__ float g_cB[NC * NCHAIN];
__device__ float g_cr[NC * NCHAIN];

// ---------------- helpers ----------------
DI uint32_t smem_u32(const void* p) {
    uint32_t a;
    asm("{ .reg .u64 t; cvta.to.shared.u64 t, %1; cvt.u32.u64 %0, t; }" : "=r"(a) : "l"(p));
    return a;
}
DI void cp16(uint32_t dst, const void* src) {
    asm volatile("cp.async.cg.shared.global [%0], [%1], 16;" :: "r"(dst), "l"(src));
}
DI void cp_commit() { asm volatile("cp.async.commit_group;" ::: "memory"); }
template <int N> DI void cp_wait() {
    asm volatile("cp.async.wait_group %0;" :: "n"(N) : "memory");
}
DI void ldsm4(uint32_t& r0, uint32_t& r1, uint32_t& r2, uint32_t& r3, uint32_t addr) {
    asm volatile("ldmatrix.sync.aligned.m8n8.x4.shared.b16 {%0,%1,%2,%3}, [%4];"
                 : "=r"(r0), "=r"(r1), "=r"(r2), "=r"(r3) : "r"(addr));
}
DI void mma_f16(float& c0, float& c1, float& c2, float& c3,
                uint32_t a0, uint32_t a1, uint32_t a2, uint32_t a3,
                uint32_t b0, uint32_t b1) {
    asm volatile(
        "mma.sync.aligned.m16n8k16.row.col.f32.f16.f16.f32 "
        "{%0,%1,%2,%3}, {%4,%5,%6,%7}, {%8,%9}, {%0,%1,%2,%3};"
        : "+f"(c0), "+f"(c1), "+f"(c2), "+f"(c3)
        : "r"(a0), "r"(a1), "r"(a2), "r"(a3), "r"(b0), "r"(b1));
}
DI float sigf(float z) { return 1.0f / (1.0f + __expf(-z)); }
DI float tanhfast(float z) { return 1.0f - 2.0f / (1.0f + __expf(2.0f * z)); }

// ---------------- prep: fp32 -> fp16 ----------------
__global__ void prep_x_kernel(const float* __restrict__ x) {
    size_t i = (size_t)blockIdx.x * blockDim.x + threadIdx.x;
    float4 v0 = reinterpret_cast<const float4*>(x)[2 * i];
    float4 v1 = reinterpret_cast<const float4*>(x)[2 * i + 1];
    __half2 h[4];
    h[0] = __floats2half2_rn(v0.x, v0.y);
    h[1] = __floats2half2_rn(v0.z, v0.w);
    h[2] = __floats2half2_rn(v1.x, v1.y);
    h[3] = __floats2half2_rn(v1.z, v1.w);
    reinterpret_cast<uint4*>(g_xh)[i] = *reinterpret_cast<uint4*>(h);
}

__global__ void prep_w_kernel(const float* __restrict__ Wf, const float* __restrict__ Wi,
                              const float* __restrict__ Wig, const float* __restrict__ Wog) {
    __shared__ float t[32][33];
    int g = blockIdx.z;
    const float* W = (g == 0) ? Wf : (g == 1) ? Wi : (g == 2) ? Wig : Wog;
    int n0 = blockIdx.x * 32, k0 = blockIdx.y * 32;
    int tx = threadIdx.x, ty = threadIdx.y;
    t[ty][tx] = W[(size_t)(k0 + ty) * 1024 + n0 + tx];
    __syncthreads();
    g_wh[(size_t)(g * 1024 + n0 + ty) * 1024 + (k0 + tx)] = __float2half_rn(t[tx][ty]);
}

// ---------------- fp16 GEMM (256x128 CTA, 16 warps, 32x64 warp tiles) ----------------
__global__ void __launch_bounds__(512, 1)
gemm_kernel(const float* __restrict__ bf, const float* __restrict__ bi,
            const float* __restrict__ big, const float* __restrict__ bog) {
    extern __shared__ __half sm[];
    const uint32_t sb = smem_u32(sm);

    const int tid  = threadIdx.x;
    const int wid  = tid >> 5, lane = tid & 31;
    const int lane4 = lane & 3, laneg = lane >> 2;
    const int warpM = wid & 7;          // 8 warps along M (32 rows each)
    const int warpN = wid >> 3;         // 2 warps along N (64 cols each)
    const int nTile = blockIdx.x;       // 0..31
    const int mTile = blockIdx.y;       // 0..127
    const int g     = nTile >> 3;       // gate
    const int nbase = (nTile & 7) * BN; // col offset inside gate

    const __half* Abase = g_xh + (size_t)mTile * BM * KTOT;
    const __half* Bbase = g_wh + ((size_t)g * DD + nbase) * KTOT;

    auto load_chunk = [&](int kc, int s) {
        const uint32_t sA = sb + s * (STAGE_H * 2);
        const uint32_t sB = sA + ASTAGE * 2;
        const __half* gA = Abase + kc * BK;
        const __half* gB = Bbase + kc * BK;
        #pragma unroll
        for (int i = 0; i < 2; i++) {                 // A: 1024 x 16B chunks
            int c = tid + i * 512;
            int row = c >> 2, seg = (c & 3) * 8;
            cp16(sA + (row * KP + seg) * 2, gA + (size_t)row * KTOT + seg);
        }
        {                                             // B: 512 x 16B chunks
            int c = tid;
            int row = c >> 2, seg = (c & 3) * 8;
            cp16(sB + (row * KP + seg) * 2, gB + (size_t)row * KTOT + seg);
        }
        cp_commit();
    };

    float acc[2][8][4];
    #pragma unroll
    for (int mf = 0; mf < 2; mf++)
        #pragma unroll
        for (int nf = 0; nf < 8; nf++)
            #pragma unroll
            for (int j = 0; j < 4; j++) acc[mf][nf][j] = 0.0f;

    // per-thread ldmatrix byte offsets (within a stage)
    uint32_t aOff[2], bOff[4];
    #pragma unroll
    for (int mf = 0; mf < 2; mf++)
        aOff[mf] = (uint32_t)(((warpM * 32 + mf * 16 + (lane & 15)) * KP + (lane >> 4) * 8) * 2);
    #pragma unroll
    for (int p = 0; p < 4; p++)
        bOff[p] = (uint32_t)(((warpN * 64 + p * 16 + (lane & 7) + (lane >> 4) * 8) * KP
                              + ((lane >> 3) & 1) * 8) * 2) + ASTAGE * 2;

    load_chunk(0, 0);
    load_chunk(1, 1);
    load_chunk(2, 2);
    load_chunk(3, 3);

    for (int kc = 0; kc < NKC; kc++) {
        const int s = kc % STAGES;
        if (kc + 3 < NKC)      cp_wait<3>();
        else if (kc + 2 < NKC) cp_wait<2>();
        else if (kc + 1 < NKC) cp_wait<1>();
        else                   cp_wait<0>();
        __syncthreads();
        if (kc + 4 < NKC) load_chunk(kc + 4, (kc + 4) % STAGES);

        const uint32_t st = sb + s * (STAGE_H * 2);
        #pragma unroll
        for (int kf = 0; kf < 2; kf++) {
            const uint32_t kb = kf * 32;              // 16 halfs = 32 bytes
            uint32_t a[2][4];
            #pragma unroll
            for (int mf = 0; mf < 2; mf++)
                ldsm4(a[mf][0], a[mf][1], a[mf][2], a[mf][3], st + aOff[mf] + kb);
            uint32_t b[8][2];
            #pragma unroll
            for (int p = 0; p < 4; p++)
                ldsm4(b[2 * p][0], b[2 * p][1], b[2 * p + 1][0], b[2 * p + 1][1],
                      st + bOff[p] + kb);
            #pragma unroll
            for (int mf = 0; mf < 2; mf++)
                #pragma unroll
                for (int nf = 0; nf < 8; nf++)
                    mma_f16(acc[mf][nf][0], acc[mf][nf][1], acc[mf][nf][2], acc[mf][nf][3],
                            a[mf][0], a[mf][1], a[mf][2], a[mf][3],
                            b[nf][0], b[nf][1]);
        }
    }

    // epilogue: bias + activation, write fp16 gate array
    const float* bias = (g == 0) ? bf : (g == 1) ? bi : (g == 2) ? big : bog;
    __half* oA = (g == 0) ? g_f : (g == 1) ? g_ti : (g == 2) ? g_si : g_og;
    const bool isTanh = (g == 1);
    #pragma unroll
    for (int nf = 0; nf < 8; nf++) {
        const int d = nbase + warpN * 64 + nf * 8 + 2 * lane4;
        const float bz0 = bias[d], bz1 = bias[d + 1];
        #pragma unroll
        for (int mf = 0; mf < 2; mf++) {
            const int r0 = mTile * BM + warpM * 32 + mf * 16 + laneg;
            float z0 = acc[mf][nf][0] + bz0;
            float z1 = acc[mf][nf][1] + bz1;
            float z2 = acc[mf][nf][2] + bz0;
            float z3 = acc[mf][nf][3] + bz1;
            float o0, o1, o2, o3;
            if (isTanh) { o0 = tanhfast(z0); o1 = tanhfast(z1);
                          o2 = tanhfast(z2); o3 = tanhfast(z3); }
            else        { o0 = sigf(z0); o1 = sigf(z1);
                          o2 = sigf(z2); o3 = sigf(z3); }
            *reinterpret_cast<__half2*>(oA + (size_t)r0 * DD + d) = __floats2half2_rn(o0, o1);
            *reinterpret_cast<__half2*>(oA + (size_t)(r0 + 8) * DD + d) = __floats2half2_rn(o2, o3);
        }
    }
}

// ---------------- scan kernels (2 chains per thread via half2) ----------------
__global__ void scan_pass1() {
    int p = blockIdx.x * 256 + threadIdx.x;         // 0..511 half2 lane
    int c = blockIdx.y, b = blockIdx.z;
    size_t base = ((size_t)(b * LL + c * CL)) * (DD / 2) + p;
    const __half2* F2p  = reinterpret_cast<const __half2*>(g_f);
    const __half2* Ti2p = reinterpret_cast<const __half2*>(g_ti);
    const __half2* Si2p = reinterpret_cast<const __half2*>(g_si);
    float2 a = make_float2(1.0f, 1.0f);
    float2 s = make_float2(0.0f, 0.0f);
    for (int t = 0; t < CL; t++) {
        size_t idx = base + (size_t)t * (DD / 2);
        float2 F = __half22float2(F2p[idx]);
        float2 Ti = __half22float2(Ti2p[idx]);
        float2 Si = __half22float2(Si2p[idx]);
        s.x = fmaf(F.x, s.x, Ti.x * Si.x);
        s.y = fmaf(F.y, s.y, Ti.y * Si.y);
        a.x *= F.x; a.y *= F.y;
    }
    int chain = b * DD + 2 * p;
    g_cA[c * NCHAIN + chain]     = a.x;
    g_cA[c * NCHAIN + chain + 1] = a.y;
    g_cB[c * NCHAIN + chain]     = s.x;
    g_cB[c * NCHAIN + chain + 1] = s.y;
}

__global__ void scan_pass2(const float* __restrict__ lh) {
    int chain = blockIdx.x * 256 + threadIdx.x;     // 0..4095
    float carry = lh[chain & (DD - 1)];
    for (int c = 0; c < NC; c++) {
        g_cr[c * NCHAIN + chain] = carry;
        carry = fmaf(g_cA[c * NCHAIN + chain], carry, g_cB[c * NCHAIN + chain]);
    }
}

__global__ void scan_pass3(float* __restrict__ y) {
    int p = blockIdx.x * 256 + threadIdx.x;         // 0..511 half2 lane
    int c = blockIdx.y, b = blockIdx.z;
    int chain = b * DD + 2 * p;
    float2 h;
    h.x = g_cr[c * NCHAIN + chain];
    h.y = g_cr[c * NCHAIN + chain + 1];
    size_t base = ((size_t)(b * LL + c * CL)) * (DD / 2) + p;
    const __half2* F2p  = reinterpret_cast<const __half2*>(g_f);
    const __half2* Ti2p = reinterpret_cast<const __half2*>(g_ti);
    const __half2* Si2p = reinterpret_cast<const __half2*>(g_si);
    const __half2* Og2p = reinterpret_cast<const __half2*>(g_og);
    for (int t = 0; t < CL; t++) {
        size_t idx = base + (size_t)t * (DD / 2);
        float2 F = __half22float2(F2p[idx]);
        float2 Ti = __half22float2(Ti2p[idx]);
        float2 Si = __half22float2(Si2p[idx]);
        float2 Og = __half22float2(Og2p[idx]);
        h.x = fmaf(F.x, h.x, Ti.x * Si.x);
        h.y = fmaf(F.y, h.y, Ti.y * Si.y);
        float2 o;
        o.x = tanhfast(h.x) * Og.x;
        o.y = tanhfast(h.y) * Og.y;
        reinterpret_cast<float2*>(y)[idx] = o;
    }
}

// ---------------- launch ----------------
extern "C" void kernel_launch(void* const* d_in, const int* in_sizes, int n_in,
                              void* d_out, int out_size) {
    const float* x   = (const float*)d_in[0];
    const float* Wf  = (const float*)d_in[1];
    const float* bf  = (const float*)d_in[2];
    const float* Wi  = (const float*)d_in[3];
    const float* bi  = (const float*)d_in[4];
    const float* Wig = (const float*)d_in[5];
    const float* big = (const float*)d_in[6];
    const float* Wog = (const float*)d_in[7];
    const float* bog = (const float*)d_in[8];
    const float* lh  = (const float*)d_in[9];
    float* y = (float*)d_out;

    cudaFuncSetAttribute(gemm_kernel, cudaFuncAttributeMaxDynamicSharedMemorySize, SMEM_BYTES);

    prep_x_kernel<<<16384, 256>>>(x);
    prep_w_kernel<<<dim3(32, 32, 4), dim3(32, 32)>>>(Wf, Wi, Wig, Wog);
    gemm_kernel<<<dim3(32, 128), 512, SMEM_BYTES>>>(bf, bi, big, bog);
    scan_pass1<<<dim3(2, NC, 4), 256>>>();
    scan_pass2<<<16, 256>>>(lh);
    scan_pass3<<<dim3(2, NC, 4), 256>>>(y);
}

// round 8
// speedup vs baseline: 1.4342x; 1.2363x over previous
#include <cuda_runtime.h>
#include <cuda_fp16.h>
#include <cstdint>
#include <math.h>

#define DI __device__ __forceinline__

// ---------------- problem sizes ----------------
constexpr int BB   = 4;
constexpr int LL   = 8192;
constexpr int DD   = 1024;
constexpr int MTOT = BB * LL;     // 32768
constexpr int KTOT = 1024;

// GEMM tiling: 128x128 CTA tile, 8 warps (4Mx2N), 32x64 warp tiles, BK=64, 2 CTAs/SM
constexpr int BM = 128, BN = 128, BK = 64;
constexpr int NKC = KTOT / BK;            // 16
constexpr int KP  = 72;                   // smem pitch in halfs (144B rows, conflict-free)
constexpr int ASTAGE = BM * KP;           // 9216 halfs
constexpr int BSTAGE = BN * KP;           // 9216 halfs
constexpr int STAGE_H = ASTAGE + BSTAGE;  // 18432 halfs = 36864 B
constexpr int STAGES = 3;
constexpr int SMEM_BYTES = STAGES * STAGE_H * 2;   // 110592 B -> 2 CTAs/SM

// scan chunking
constexpr int NC = 64;
constexpr int CL = LL / NC;               // 128
constexpr int NCHAIN = BB * DD;           // 4096

// ---------------- device scratch ----------------
__device__ __half g_xh[(size_t)MTOT * KTOT];    // fp16 x
__device__ __half g_wh[(size_t)4 * DD * KTOT];  // fp16 weights, [gate][n][k]
__device__ __half g_f [(size_t)MTOT * DD];      // gates stored fp16
__device__ __half g_ti[(size_t)MTOT * DD];
__device__ __half g_si[(size_t)MTOT * DD];
__device__ __half g_og[(size_t)MTOT * DD];
__device__ float g_cA[NC * NCHAIN];
__device__ float g_cB[NC * NCHAIN];
__device__ float g_cr[NC * NCHAIN];

// ---------------- helpers ----------------
DI uint32_t smem_u32(const void* p) {
    uint32_t a;
    asm("{ .reg .u64 t; cvta.to.shared.u64 t, %1; cvt.u32.u64 %0, t; }" : "=r"(a) : "l"(p));
    return a;
}
DI void cp16(uint32_t dst, const void* src) {
    asm volatile("cp.async.cg.shared.global [%0], [%1], 16;" :: "r"(dst), "l"(src));
}
DI void cp_commit() { asm volatile("cp.async.commit_group;" ::: "memory"); }
template <int N> DI void cp_wait() {
    asm volatile("cp.async.wait_group %0;" :: "n"(N) : "memory");
}
DI void ldsm4(uint32_t& r0, uint32_t& r1, uint32_t& r2, uint32_t& r3, uint32_t addr) {
    asm volatile("ldmatrix.sync.aligned.m8n8.x4.shared.b16 {%0,%1,%2,%3}, [%4];"
                 : "=r"(r0), "=r"(r1), "=r"(r2), "=r"(r3) : "r"(addr));
}
DI void mma_f16(float& c0, float& c1, float& c2, float& c3,
                uint32_t a0, uint32_t a1, uint32_t a2, uint32_t a3,
                uint32_t b0, uint32_t b1) {
    asm volatile(
        "mma.sync.aligned.m16n8k16.row.col.f32.f16.f16.f32 "
        "{%0,%1,%2,%3}, {%4,%5,%6,%7}, {%8,%9}, {%0,%1,%2,%3};"
        : "+f"(c0), "+f"(c1), "+f"(c2), "+f"(c3)
        : "r"(a0), "r"(a1), "r"(a2), "r"(a3), "r"(b0), "r"(b1));
}
DI float sigf(float z) { return 1.0f / (1.0f + __expf(-z)); }
DI float tanhfast(float z) { return 1.0f - 2.0f / (1.0f + __expf(2.0f * z)); }

// ---------------- prep: fp32 -> fp16 ----------------
__global__ void prep_x_kernel(const float* __restrict__ x) {
    size_t i = (size_t)blockIdx.x * blockDim.x + threadIdx.x;
    float4 v0 = reinterpret_cast<const float4*>(x)[2 * i];
    float4 v1 = reinterpret_cast<const float4*>(x)[2 * i + 1];
    __half2 h[4];
    h[0] = __floats2half2_rn(v0.x, v0.y);
    h[1] = __floats2half2_rn(v0.z, v0.w);
    h[2] = __floats2half2_rn(v1.x, v1.y);
    h[3] = __floats2half2_rn(v1.z, v1.w);
    reinterpret_cast<uint4*>(g_xh)[i] = *reinterpret_cast<uint4*>(h);
}

__global__ void prep_w_kernel(const float* __restrict__ Wf, const float* __restrict__ Wi,
                              const float* __restrict__ Wig, const float* __restrict__ Wog) {
    __shared__ float t[32][33];
    int g = blockIdx.z;
    const float* W = (g == 0) ? Wf : (g == 1) ? Wi : (g == 2) ? Wig : Wog;
    int n0 = blockIdx.x * 32, k0 = blockIdx.y * 32;
    int tx = threadIdx.x, ty = threadIdx.y;
    t[ty][tx] = W[(size_t)(k0 + ty) * 1024 + n0 + tx];
    __syncthreads();
    g_wh[(size_t)(g * 1024 + n0 + ty) * 1024 + (k0 + tx)] = __float2half_rn(t[tx][ty]);
}

// ---------------- fp16 GEMM (128x128 CTA, 8 warps, 32x64 warp tiles, BK=64) ----------------
__global__ void __launch_bounds__(256, 2)
gemm_kernel(const float* __restrict__ bf, const float* __restrict__ bi,
            const float* __restrict__ big, const float* __restrict__ bog) {
    extern __shared__ __half sm[];
    const uint32_t sb = smem_u32(sm);

    const int tid  = threadIdx.x;
    const int wid  = tid >> 5, lane = tid & 31;
    const int lane4 = lane & 3, laneg = lane >> 2;
    const int warpM = wid & 3;          // 4 warps along M (32 rows each)
    const int warpN = wid >> 2;         // 2 warps along N (64 cols each)
    const int nTile = blockIdx.x;       // 0..31
    const int mTile = blockIdx.y;       // 0..255
    const int g     = nTile >> 3;       // gate
    const int nbase = (nTile & 7) * BN; // col offset inside gate

    const __half* Abase = g_xh + (size_t)mTile * BM * KTOT;
    const __half* Bbase = g_wh + ((size_t)g * DD + nbase) * KTOT;

    auto load_chunk = [&](int kc, int s) {
        const uint32_t sA = sb + s * (STAGE_H * 2);
        const uint32_t sB = sA + ASTAGE * 2;
        const __half* gA = Abase + kc * BK;
        const __half* gB = Bbase + kc * BK;
        #pragma unroll
        for (int i = 0; i < 4; i++) {                 // A: 1024 x 16B chunks (128 rows x 64 halfs)
            int c = tid + i * 256;
            int row = c >> 3, seg = (c & 7) * 8;
            cp16(sA + (row * KP + seg) * 2, gA + (size_t)row * KTOT + seg);
        }
        #pragma unroll
        for (int i = 0; i < 4; i++) {                 // B: 1024 x 16B chunks
            int c = tid + i * 256;
            int row = c >> 3, seg = (c & 7) * 8;
            cp16(sB + (row * KP + seg) * 2, gB + (size_t)row * KTOT + seg);
        }
        cp_commit();
    };

    float acc[2][8][4];
    #pragma unroll
    for (int mf = 0; mf < 2; mf++)
        #pragma unroll
        for (int nf = 0; nf < 8; nf++)
            #pragma unroll
            for (int j = 0; j < 4; j++) acc[mf][nf][j] = 0.0f;

    // per-thread ldmatrix byte offsets (within a stage)
    uint32_t aOff[2], bOff[4];
    #pragma unroll
    for (int mf = 0; mf < 2; mf++)
        aOff[mf] = (uint32_t)(((warpM * 32 + mf * 16 + (lane & 15)) * KP + (lane >> 4) * 8) * 2);
    #pragma unroll
    for (int p = 0; p < 4; p++)
        bOff[p] = (uint32_t)(((warpN * 64 + p * 16 + (lane & 7) + (lane >> 4) * 8) * KP
                              + ((lane >> 3) & 1) * 8) * 2) + ASTAGE * 2;

    load_chunk(0, 0);
    load_chunk(1, 1);

    for (int kc = 0; kc < NKC; kc++) {
        const int s = kc % STAGES;
        if (kc + 1 < NKC) cp_wait<1>(); else cp_wait<0>();
        __syncthreads();
        if (kc + 2 < NKC) load_chunk(kc + 2, (kc + 2) % STAGES);

        const uint32_t st = sb + s * (STAGE_H * 2);
        #pragma unroll
        for (int kf = 0; kf < 4; kf++) {
            const uint32_t kb = kf * 32;              // 16 halfs = 32 bytes
            uint32_t a[2][4];
            #pragma unroll
            for (int mf = 0; mf < 2; mf++)
                ldsm4(a[mf][0], a[mf][1], a[mf][2], a[mf][3], st + aOff[mf] + kb);
            uint32_t b[8][2];
            #pragma unroll
            for (int p = 0; p < 4; p++)
                ldsm4(b[2 * p][0], b[2 * p][1], b[2 * p + 1][0], b[2 * p + 1][1],
                      st + bOff[p] + kb);
            #pragma unroll
            for (int mf = 0; mf < 2; mf++)
                #pragma unroll
                for (int nf = 0; nf < 8; nf++)
                    mma_f16(acc[mf][nf][0], acc[mf][nf][1], acc[mf][nf][2], acc[mf][nf][3],
                            a[mf][0], a[mf][1], a[mf][2], a[mf][3],
                            b[nf][0], b[nf][1]);
        }
    }

    // epilogue: bias + activation, write fp16 gate array
    const float* bias = (g == 0) ? bf : (g == 1) ? bi : (g == 2) ? big : bog;
    __half* oA = (g == 0) ? g_f : (g == 1) ? g_ti : (g == 2) ? g_si : g_og;
    const bool isTanh = (g == 1);
    #pragma unroll
    for (int nf = 0; nf < 8; nf++) {
        const int d = nbase + warpN * 64 + nf * 8 + 2 * lane4;
        const float bz0 = bias[d], bz1 = bias[d + 1];
        #pragma unroll
        for (int mf = 0; mf < 2; mf++) {
            const int r0 = mTile * BM + warpM * 32 + mf * 16 + laneg;
            float z0 = acc[mf][nf][0] + bz0;
            float z1 = acc[mf][nf][1] + bz1;
            float z2 = acc[mf][nf][2] + bz0;
            float z3 = acc[mf][nf][3] + bz1;
            float o0, o1, o2, o3;
            if (isTanh) { o0 = tanhfast(z0); o1 = tanhfast(z1);
                          o2 = tanhfast(z2); o3 = tanhfast(z3); }
            else        { o0 = sigf(z0); o1 = sigf(z1);
                          o2 = sigf(z2); o3 = sigf(z3); }
            *reinterpret_cast<__half2*>(oA + (size_t)r0 * DD + d) = __floats2half2_rn(o0, o1);
            *reinterpret_cast<__half2*>(oA + (size_t)(r0 + 8) * DD + d) = __floats2half2_rn(o2, o3);
        }
    }
}

// ---------------- scan kernels (2 chains per thread via half2) ----------------
__global__ void scan_pass1() {
    int p = blockIdx.x * 256 + threadIdx.x;         // 0..511 half2 lane
    int c = blockIdx.y, b = blockIdx.z;
    size_t base = ((size_t)(b * LL + c * CL)) * (DD / 2) + p;
    const __half2* F2p  = reinterpret_cast<const __half2*>(g_f);
    const __half2* Ti2p = reinterpret_cast<const __half2*>(g_ti);
    const __half2* Si2p = reinterpret_cast<const __half2*>(g_si);
    float2 a = make_float2(1.0f, 1.0f);
    float2 s = make_float2(0.0f, 0.0f);
    for (int t = 0; t < CL; t++) {
        size_t idx = base + (size_t)t * (DD / 2);
        float2 F = __half22float2(F2p[idx]);
        float2 Ti = __half22float2(Ti2p[idx]);
        float2 Si = __half22float2(Si2p[idx]);
        s.x = fmaf(F.x, s.x, Ti.x * Si.x);
        s.y = fmaf(F.y, s.y, Ti.y * Si.y);
        a.x *= F.x; a.y *= F.y;
    }
    int chain = b * DD + 2 * p;
    g_cA[c * NCHAIN + chain]     = a.x;
    g_cA[c * NCHAIN + chain + 1] = a.y;
    g_cB[c * NCHAIN + chain]     = s.x;
    g_cB[c * NCHAIN + chain + 1] = s.y;
}

__global__ void scan_pass2(const float* __restrict__ lh) {
    int chain = blockIdx.x * 256 + threadIdx.x;     // 0..4095
    float carry = lh[chain & (DD - 1)];
    for (int c = 0; c < NC; c++) {
        g_cr[c * NCHAIN + chain] = carry;
        carry = fmaf(g_cA[c * NCHAIN + chain], carry, g_cB[c * NCHAIN + chain]);
    }
}

__global__ void scan_pass3(float* __restrict__ y) {
    int p = blockIdx.x * 256 + threadIdx.x;         // 0..511 half2 lane
    int c = blockIdx.y, b = blockIdx.z;
    int chain = b * DD + 2 * p;
    float2 h;
    h.x = g_cr[c * NCHAIN + chain];
    h.y = g_cr[c * NCHAIN + chain + 1];
    size_t base = ((size_t)(b * LL + c * CL)) * (DD / 2) + p;
    const __half2* F2p  = reinterpret_cast<const __half2*>(g_f);
    const __half2* Ti2p = reinterpret_cast<const __half2*>(g_ti);
    const __half2* Si2p = reinterpret_cast<const __half2*>(g_si);
    const __half2* Og2p = reinterpret_cast<const __half2*>(g_og);
    for (int t = 0; t < CL; t++) {
        size_t idx = base + (size_t)t * (DD / 2);
        float2 F = __half22float2(F2p[idx]);
        float2 Ti = __half22float2(Ti2p[idx]);
        float2 Si = __half22float2(Si2p[idx]);
        float2 Og = __half22float2(Og2p[idx]);
        h.x = fmaf(F.x, h.x, Ti.x * Si.x);
        h.y = fmaf(F.y, h.y, Ti.y * Si.y);
        float2 o;
        o.x = tanhfast(h.x) * Og.x;
        o.y = tanhfast(h.y) * Og.y;
        reinterpret_cast<float2*>(y)[idx] = o;
    }
}

// ---------------- launch ----------------
extern "C" void kernel_launch(void* const* d_in, const int* in_sizes, int n_in,
                              void* d_out, int out_size) {
    const float* x   = (const float*)d_in[0];
    const float* Wf  = (const float*)d_in[1];
    const float* bf  = (const float*)d_in[2];
    const float* Wi  = (const float*)d_in[3];
    const float* bi  = (const float*)d_in[4];
    const float* Wig = (const float*)d_in[5];
    const float* big = (const float*)d_in[6];
    const float* Wog = (const float*)d_in[7];
    const float* bog = (const float*)d_in[8];
    const float* lh  = (const float*)d_in[9];
    float* y = (float*)d_out;

    cudaFuncSetAttribute(gemm_kernel, cudaFuncAttributeMaxDynamicSharedMemorySize, SMEM_BYTES);

    prep_x_kernel<<<16384, 256>>>(x);
    prep_w_kernel<<<dim3(32, 32, 4), dim3(32, 32)>>>(Wf, Wi, Wig, Wog);
    gemm_kernel<<<dim3(32, 256), 256, SMEM_BYTES>>>(bf, bi, big, bog);
    scan_pass1<<<dim3(2, NC, 4), 256>>>();
    scan_pass2<<<16, 256>>>(lh);
    scan_pass3<<<dim3(2, NC, 4), 256>>>(y);
}